// round 12
// baseline (speedup 1.0000x reference)
#include <cuda_runtime.h>
#include <math.h>

#define N 32
#define LDT 33                 // padded tile leading dim
#define WARPS_PER_CTA 4
#define NTHREADS (WARPS_PER_CTA * 32)
#define NSWEEP 6
#define MINSWEEP 3
#define JTOL2 1e-6f            // squared scale-free residual tolerance (1e-3^2)
#define EPS 1e-6f
#define NB_BANDS 9
#define T_DIM 128
#define B_DIM 8

typedef unsigned long long ull;

// ---- packed 2xfp32 helpers (Blackwell FFMA2 path, PTX-only) ----
__device__ __forceinline__ ull pack2(float x, float y)
{ ull r; asm("mov.b64 %0, {%1, %2};" : "=l"(r) : "f"(x), "f"(y)); return r; }
__device__ __forceinline__ void unpack2(ull v, float& x, float& y)
{ asm("mov.b64 {%0, %1}, %2;" : "=f"(x), "=f"(y) : "l"(v)); }
__device__ __forceinline__ ull mul2(ull a, ull b)
{ ull d; asm("mul.rn.f32x2 %0, %1, %2;" : "=l"(d) : "l"(a), "l"(b)); return d; }
__device__ __forceinline__ ull fma2(ull a, ull b, ull c)
{ ull d; asm("fma.rn.f32x2 %0, %1, %2, %3;" : "=l"(d) : "l"(a), "l"(b), "l"(c)); return d; }
__device__ __forceinline__ ull add2(ull a, ull b)
{ ull d; asm("add.rn.f32x2 %0, %1, %2;" : "=l"(d) : "l"(a), "l"(b)); return d; }

// Jacobi rotation for implicit 2x2 [[np, bpq],[bpq, nq]].
// t = sign(d) * b / (|d| + sqrt(d^2 + b^2)),  d = (nq - np)/2   (exact algebra,
// identical to the tau form; 3 MUFUs, shorter dependency chain, no clamps).
__device__ __forceinline__ void fastrot(float np, float nq, float bpq,
                                        float& c, float& s)
{
    if (fabsf(bpq) > 1e-20f) {
        float d    = 0.5f * (nq - np);
        float r2   = fmaf(d, d, bpq * bpq);
        float rinv = rsqrtf(r2);                        // MUFU 1
        float r    = r2 * rinv;
        float den  = fabsf(d) + r;
        float t    = bpq * __frcp_rn(den);              // MUFU 2
        t = (d >= 0.0f) ? t : -t;
        c = rsqrtf(fmaf(t, t, 1.0f));                   // MUFU 3
        s = t * c;
    } else { c = 1.0f; s = 0.0f; }
}

// Warp-cooperative in-place Cholesky (lower) of SPD 32x32 in smem. lane = row.
__device__ __forceinline__ void warp_chol(float* S, int lane)
{
    for (int k = 0; k < N; ++k) {
        float akk = S[k * LDT + k];
        float inv = rsqrtf(fmaxf(akk, 1e-12f));
        __syncwarp();
        float lik = 0.0f;
        if (lane >= k) {
            float v = S[lane * LDT + k];
            lik = (lane == k) ? akk * inv : v * inv;
            S[lane * LDT + k] = lik;
        }
        __syncwarp();
        if (lane > k) {
            for (int j = k + 1; j <= lane; ++j)
                S[lane * LDT + j] -= lik * S[j * LDT + k];
        }
        __syncwarp();
    }
}

// ---------------------------------------------------------------------------
// One WARP per output site:
//   L = chol(A); Lb = chol(B); G = L^{-1} Lb  (lane = column, registers)
//   one-sided Jacobi on G's columns (XOR ordering, packed f32x2 math,
//   software-pipelined shfl exchange)
//   mean = Z Z^T with z_c = L g_c * lambda_c^{(w2-1)/2}
// Requires K == 2.
// ---------------------------------------------------------------------------
__global__ void __launch_bounds__(NTHREADS, 7)
wfm_kernel(const float* __restrict__ x, const float* __restrict__ rw,
           float* __restrict__ out, int t_out)
{
    __shared__ float tiles[WARPS_PER_CTA][2][N * LDT];

    const int lane = threadIdx.x & 31;
    const int wrp  = threadIdx.x >> 5;
    float* sA = tiles[wrp][0];                 // A -> L  (upper zeroed later)
    float* sB = tiles[wrp][1];                 // B -> Lb -> Z

    const int site = blockIdx.x * WARPS_PER_CTA + wrp;
    const int band = site % NB_BANDS;
    const int tmp  = site / NB_BANDS;
    const int tt   = tmp % t_out;
    const int b    = tmp / t_out;

    const float* Ma = x + ((size_t)(b * T_DIM + tt) * NB_BANDS + band) * (size_t)(N * N);
    const float* Mb = Ma + (size_t)NB_BANDS * N * N;

    // softmax weight w2 (K == 2)
    float r0 = rw[0], r1 = rw[1];
    float mx = fmaxf(r0, r1);
    float e0 = __expf(r0 - mx), e1 = __expf(r1 - mx);
    const float w2 = e1 / (e0 + e1);

    // load A, B into per-warp tiles (coalesced)
#pragma unroll
    for (int t = 0; t < N; ++t) {
        sA[t * LDT + lane] = Ma[t * N + lane];
        sB[t * LDT + lane] = Mb[t * N + lane];
    }
    __syncwarp();

    warp_chol(sA, lane);                       // sA lower = L
    warp_chol(sB, lane);                       // sB lower = Lb

    // zero strict upper of sA (so Z = L*u can be unconditional later)
#pragma unroll
    for (int j = 0; j < N; ++j)
        if (j > lane) sA[lane * LDT + j] = 0.0f;
    __syncwarp();

    // G = L^{-1} Lb, lane = column c. Lower triangular: u[k] = 0 for k < c.
    float uu[N];
#pragma unroll
    for (int k = 0; k < N; ++k) {
        float acc = sB[k * LDT + lane];
#pragma unroll
        for (int j = 0; j < k; ++j)
            acc -= sA[k * LDT + j] * uu[j];    // broadcast reads of L row k
        float val = acc * __frcp_rn(sA[k * LDT + k]);
        uu[k] = (k >= lane) ? val : 0.0f;
    }

    // pack column into 16 x f32x2
    ull u2[N / 2];
#pragma unroll
    for (int i = 0; i < N / 2; ++i) u2[i] = pack2(uu[2 * i], uu[2 * i + 1]);

    float nu;                                  // ||u||^2, maintained exactly
    {
        ull acc = 0ull;
#pragma unroll
        for (int i = 0; i < N / 2; ++i) acc = fma2(u2[i], u2[i], acc);
        float ax, ay; unpack2(acc, ax, ay);
        nu = ax + ay;
    }

    // ---------------- one-sided Jacobi, XOR ordering, pipelined ------------
    // Prefetch partner data for the first round (m = 1).
    ull pu2[N / 2];
#pragma unroll
    for (int i = 0; i < N / 2; ++i)
        pu2[i] = __shfl_xor_sync(0xffffffffu, u2[i], 1);
    float pn = __shfl_xor_sync(0xffffffffu, nu, 1);

#pragma unroll 1
    for (int sweep = 0; sweep < NSWEEP; ++sweep) {
        bool bad = false;
#pragma unroll 1
        for (int m = 1; m < 32; ++m) {
            const int partner = lane ^ m;
            const int mnext   = (m == 31) ? 1 : m + 1;

            // pair dot, 4 parallel chains (same grouping in both pair lanes)
            ull a0 = 0ull, a1 = 0ull, a2 = 0ull, a3 = 0ull;
#pragma unroll
            for (int i = 0; i < N / 2; i += 4) {
                a0 = fma2(u2[i + 0], pu2[i + 0], a0);
                a1 = fma2(u2[i + 1], pu2[i + 1], a1);
                a2 = fma2(u2[i + 2], pu2[i + 2], a2);
                a3 = fma2(u2[i + 3], pu2[i + 3], a3);
            }
            ull dsum = add2(add2(a0, a1), add2(a2, a3));
            float dx, dy; unpack2(dsum, dx, dy);
            float bu = dx + dy;

            bool isp = lane < partner;
            bad |= (bu * bu > nu * pn * JTOL2);

            float np_ = isp ? nu : pn;
            float nq_ = isp ? pn : nu;

            float c, s;
            fastrot(np_, nq_, bu, c, s);
            float ss = isp ? -s : s;

            ull c2  = pack2(c, c);
            ull ss2 = pack2(ss, ss);

            // exact norm rotation identity
            nu = c * c * nu + s * s * pn + 2.0f * ss * c * bu;

            // fused update + next-round shfl (overlaps shfl latency with FMAs)
#pragma unroll
            for (int i = 0; i < N / 2; ++i) {
                u2[i]  = fma2(ss2, pu2[i], mul2(c2, u2[i]));
                pu2[i] = __shfl_xor_sync(0xffffffffu, u2[i], mnext);
            }
            pn = __shfl_xor_sync(0xffffffffu, nu, mnext);
        }
        if (sweep >= MINSWEEP - 1 && !__any_sync(0xffffffffu, bad)) break;
    }

    // eigenvalue = exact final column norm; scale: z = L u * lam^{(w2-1)/2}
    float lam;
    {
        ull acc = 0ull;
#pragma unroll
        for (int i = 0; i < N / 2; ++i) acc = fma2(u2[i], u2[i], acc);
        float ax, ay; unpack2(acc, ax, ay);
        lam = fmaxf(ax + ay, EPS);
    }
    float scale = __expf(0.5f * (w2 - 1.0f) * __logf(lam));
    {
        ull sc2 = pack2(scale, scale);
#pragma unroll
        for (int i = 0; i < N / 2; ++i) u2[i] = mul2(sc2, u2[i]);
    }

    // unpack for the smem products
#pragma unroll
    for (int i = 0; i < N / 2; ++i) unpack2(u2[i], uu[2 * i], uu[2 * i + 1]);

    __syncwarp();
    // Z = L * u (store columns into sB, reuse tile)
    for (int i = 0; i < N; ++i) {
        float acc = 0.0f;
#pragma unroll
        for (int j = 0; j < N; ++j)
            acc = fmaf(sA[i * LDT + j], uu[j], acc);  // upper of L is zeroed
        sB[i * LDT + lane] = acc;
    }
    __syncwarp();

    // mean[i][lane] = sum_c Z[i][c] * Z[lane][c]
    float rr[N];
#pragma unroll
    for (int c = 0; c < N; ++c) rr[c] = sB[lane * LDT + c];

    float* o = out + (size_t)site * (N * N);
    for (int i = 0; i < N; ++i) {
        float acc = 0.0f;
#pragma unroll
        for (int c = 0; c < N; ++c)
            acc = fmaf(sB[i * LDT + c], rr[c], acc);  // broadcast reads
        o[i * N + lane] = acc;                        // coalesced
    }
}

extern "C" void kernel_launch(void* const* d_in, const int* in_sizes, int n_in,
                              void* d_out, int out_size)
{
    const float* x  = (const float*)d_in[0];
    const float* rw = (const float*)d_in[1];
    float* out = (float*)d_out;

    const int K     = in_sizes[1];               // KERNEL_SIZE (= 2 for this problem)
    const int t_out = T_DIM - K + 1;             // 127
    const int sites = B_DIM * t_out * NB_BANDS;  // 9144
    const int nblocks = (sites + WARPS_PER_CTA - 1) / WARPS_PER_CTA;  // 2286

    wfm_kernel<<<nblocks, NTHREADS>>>(x, rw, out, t_out);
}

// round 14
// speedup vs baseline: 1.1770x; 1.1770x over previous
#include <cuda_runtime.h>
#include <math.h>

#define N 32
#define LDT 33                 // padded tile leading dim
#define WARPS_PER_CTA 4
#define NTHREADS (WARPS_PER_CTA * 32)
#define NSWEEP 6
#define MINSWEEP 3
#define JTOL2 1e-6f            // squared scale-free residual tolerance (1e-3^2)
#define EPS 1e-6f
#define NB_BANDS 9
#define T_DIM 128
#define B_DIM 8

typedef unsigned long long ull;

// ---- packed 2xfp32 helpers (Blackwell FFMA2 path, PTX-only) ----
__device__ __forceinline__ ull pack2(float x, float y)
{ ull r; asm("mov.b64 %0, {%1, %2};" : "=l"(r) : "f"(x), "f"(y)); return r; }
__device__ __forceinline__ void unpack2(ull v, float& x, float& y)
{ asm("mov.b64 {%0, %1}, %2;" : "=f"(x), "=f"(y) : "l"(v)); }
__device__ __forceinline__ ull mul2(ull a, ull b)
{ ull d; asm("mul.rn.f32x2 %0, %1, %2;" : "=l"(d) : "l"(a), "l"(b)); return d; }
__device__ __forceinline__ ull fma2(ull a, ull b, ull c)
{ ull d; asm("fma.rn.f32x2 %0, %1, %2, %3;" : "=l"(d) : "l"(a), "l"(b), "l"(c)); return d; }
__device__ __forceinline__ ull add2(ull a, ull b)
{ ull d; asm("add.rn.f32x2 %0, %1, %2;" : "=l"(d) : "l"(a), "l"(b)); return d; }

// Jacobi rotation for implicit 2x2 [[np, bpq],[bpq, nq]].
// t = sign(d) * b / (|d| + sqrt(d^2 + b^2)),  d = (nq - np)/2   (exact algebra,
// identical to the tau form; 3 MUFUs, shorter dependency chain, no clamps).
__device__ __forceinline__ void fastrot(float np, float nq, float bpq,
                                        float& c, float& s)
{
    if (fabsf(bpq) > 1e-20f) {
        float d    = 0.5f * (nq - np);
        float r2   = fmaf(d, d, bpq * bpq);
        float rinv = rsqrtf(r2);                        // MUFU 1
        float r    = r2 * rinv;
        float den  = fabsf(d) + r;
        float t    = bpq * __frcp_rn(den);              // MUFU 2
        t = (d >= 0.0f) ? t : -t;
        c = rsqrtf(fmaf(t, t, 1.0f));                   // MUFU 3
        s = t * c;
    } else { c = 1.0f; s = 0.0f; }
}

// Warp-cooperative in-place Cholesky (lower) of SPD 32x32 in smem. lane = row.
__device__ __forceinline__ void warp_chol(float* S, int lane)
{
    for (int k = 0; k < N; ++k) {
        float akk = S[k * LDT + k];
        float inv = rsqrtf(fmaxf(akk, 1e-12f));
        __syncwarp();
        float lik = 0.0f;
        if (lane >= k) {
            float v = S[lane * LDT + k];
            lik = (lane == k) ? akk * inv : v * inv;
            S[lane * LDT + k] = lik;
        }
        __syncwarp();
        if (lane > k) {
            for (int j = k + 1; j <= lane; ++j)
                S[lane * LDT + j] -= lik * S[j * LDT + k];
        }
        __syncwarp();
    }
}

// ---------------------------------------------------------------------------
// One WARP per output site:
//   L = chol(A); Lb = chol(B); G = L^{-1} Lb  (lane = column, registers)
//   one-sided Jacobi on G's columns (XOR ordering, packed f32x2 math,
//   software-pipelined shfl exchange)
//   mean = Z Z^T with z_c = L g_c * lambda_c^{(w2-1)/2}
// Requires K == 2.
// ---------------------------------------------------------------------------
__global__ void __launch_bounds__(NTHREADS, 6)
wfm_kernel(const float* __restrict__ x, const float* __restrict__ rw,
           float* __restrict__ out, int t_out)
{
    __shared__ float tiles[WARPS_PER_CTA][2][N * LDT];

    const int lane = threadIdx.x & 31;
    const int wrp  = threadIdx.x >> 5;
    float* sA = tiles[wrp][0];                 // A -> L  (upper zeroed later)
    float* sB = tiles[wrp][1];                 // B -> Lb -> Z

    const int site = blockIdx.x * WARPS_PER_CTA + wrp;
    const int band = site % NB_BANDS;
    const int tmp  = site / NB_BANDS;
    const int tt   = tmp % t_out;
    const int b    = tmp / t_out;

    const float* Ma = x + ((size_t)(b * T_DIM + tt) * NB_BANDS + band) * (size_t)(N * N);
    const float* Mb = Ma + (size_t)NB_BANDS * N * N;

    // softmax weight w2 (K == 2)
    float r0 = rw[0], r1 = rw[1];
    float mx = fmaxf(r0, r1);
    float e0 = __expf(r0 - mx), e1 = __expf(r1 - mx);
    const float w2 = e1 / (e0 + e1);

    // load A, B into per-warp tiles (coalesced)
#pragma unroll
    for (int t = 0; t < N; ++t) {
        sA[t * LDT + lane] = Ma[t * N + lane];
        sB[t * LDT + lane] = Mb[t * N + lane];
    }
    __syncwarp();

    warp_chol(sA, lane);                       // sA lower = L
    warp_chol(sB, lane);                       // sB lower = Lb

    // zero strict upper of sA (so Z = L*u can be unconditional later)
#pragma unroll
    for (int j = 0; j < N; ++j)
        if (j > lane) sA[lane * LDT + j] = 0.0f;
    __syncwarp();

    // G = L^{-1} Lb, lane = column c. Lower triangular: u[k] = 0 for k < c.
    float uu[N];
#pragma unroll
    for (int k = 0; k < N; ++k) {
        float acc = sB[k * LDT + lane];
#pragma unroll
        for (int j = 0; j < k; ++j)
            acc -= sA[k * LDT + j] * uu[j];    // broadcast reads of L row k
        float val = acc * __frcp_rn(sA[k * LDT + k]);
        uu[k] = (k >= lane) ? val : 0.0f;
    }

    // pack column into 16 x f32x2
    ull u2[N / 2];
#pragma unroll
    for (int i = 0; i < N / 2; ++i) u2[i] = pack2(uu[2 * i], uu[2 * i + 1]);

    float nu;                                  // ||u||^2, maintained exactly
    {
        ull acc = 0ull;
#pragma unroll
        for (int i = 0; i < N / 2; ++i) acc = fma2(u2[i], u2[i], acc);
        float ax, ay; unpack2(acc, ax, ay);
        nu = ax + ay;
    }

    // ---------------- one-sided Jacobi, XOR ordering, pipelined ------------
    // Prefetch partner data for the first round (m = 1).
    ull pu2[N / 2];
#pragma unroll
    for (int i = 0; i < N / 2; ++i)
        pu2[i] = __shfl_xor_sync(0xffffffffu, u2[i], 1);
    float pn = __shfl_xor_sync(0xffffffffu, nu, 1);

#pragma unroll 1
    for (int sweep = 0; sweep < NSWEEP; ++sweep) {
        bool bad = false;
#pragma unroll 1
        for (int m = 1; m < 32; ++m) {
            const int partner = lane ^ m;
            const int mnext   = (m == 31) ? 1 : m + 1;

            // pair dot, 4 parallel chains (same grouping in both pair lanes)
            ull a0 = 0ull, a1 = 0ull, a2 = 0ull, a3 = 0ull;
#pragma unroll
            for (int i = 0; i < N / 2; i += 4) {
                a0 = fma2(u2[i + 0], pu2[i + 0], a0);
                a1 = fma2(u2[i + 1], pu2[i + 1], a1);
                a2 = fma2(u2[i + 2], pu2[i + 2], a2);
                a3 = fma2(u2[i + 3], pu2[i + 3], a3);
            }
            ull dsum = add2(add2(a0, a1), add2(a2, a3));
            float dx, dy; unpack2(dsum, dx, dy);
            float bu = dx + dy;

            bool isp = lane < partner;
            bad |= (bu * bu > nu * pn * JTOL2);

            float np_ = isp ? nu : pn;
            float nq_ = isp ? pn : nu;

            float c, s;
            fastrot(np_, nq_, bu, c, s);
            float ss = isp ? -s : s;

            ull c2  = pack2(c, c);
            ull ss2 = pack2(ss, ss);

            // exact norm rotation identity
            nu = c * c * nu + s * s * pn + 2.0f * ss * c * bu;

            // fused update + next-round shfl (overlaps shfl latency with FMAs)
#pragma unroll
            for (int i = 0; i < N / 2; ++i) {
                u2[i]  = fma2(ss2, pu2[i], mul2(c2, u2[i]));
                pu2[i] = __shfl_xor_sync(0xffffffffu, u2[i], mnext);
            }
            pn = __shfl_xor_sync(0xffffffffu, nu, mnext);
        }
        if (sweep >= MINSWEEP - 1 && !__any_sync(0xffffffffu, bad)) break;
    }

    // eigenvalue = exact final column norm; scale: z = L u * lam^{(w2-1)/2}
    float lam;
    {
        ull acc = 0ull;
#pragma unroll
        for (int i = 0; i < N / 2; ++i) acc = fma2(u2[i], u2[i], acc);
        float ax, ay; unpack2(acc, ax, ay);
        lam = fmaxf(ax + ay, EPS);
    }
    float scale = __expf(0.5f * (w2 - 1.0f) * __logf(lam));
    {
        ull sc2 = pack2(scale, scale);
#pragma unroll
        for (int i = 0; i < N / 2; ++i) u2[i] = mul2(sc2, u2[i]);
    }

    // unpack for the smem products
#pragma unroll
    for (int i = 0; i < N / 2; ++i) unpack2(u2[i], uu[2 * i], uu[2 * i + 1]);

    __syncwarp();
    // Z = L * u (store columns into sB, reuse tile)
    for (int i = 0; i < N; ++i) {
        float acc = 0.0f;
#pragma unroll
        for (int j = 0; j < N; ++j)
            acc = fmaf(sA[i * LDT + j], uu[j], acc);  // upper of L is zeroed
        sB[i * LDT + lane] = acc;
    }
    __syncwarp();

    // mean[i][lane] = sum_c Z[i][c] * Z[lane][c]
    float rr[N];
#pragma unroll
    for (int c = 0; c < N; ++c) rr[c] = sB[lane * LDT + c];

    float* o = out + (size_t)site * (N * N);
    for (int i = 0; i < N; ++i) {
        float acc = 0.0f;
#pragma unroll
        for (int c = 0; c < N; ++c)
            acc = fmaf(sB[i * LDT + c], rr[c], acc);  // broadcast reads
        o[i * N + lane] = acc;                        // coalesced
    }
}

extern "C" void kernel_launch(void* const* d_in, const int* in_sizes, int n_in,
                              void* d_out, int out_size)
{
    const float* x  = (const float*)d_in[0];
    const float* rw = (const float*)d_in[1];
    float* out = (float*)d_out;

    const int K     = in_sizes[1];               // KERNEL_SIZE (= 2 for this problem)
    const int t_out = T_DIM - K + 1;             // 127
    const int sites = B_DIM * t_out * NB_BANDS;  // 9144
    const int nblocks = (sites + WARPS_PER_CTA - 1) / WARPS_PER_CTA;  // 2286

    wfm_kernel<<<nblocks, NTHREADS>>>(x, rw, out, t_out);
}

// round 15
// speedup vs baseline: 1.2396x; 1.0532x over previous
#include <cuda_runtime.h>
#include <math.h>

#define N 32
#define LDT 33                 // padded tile leading dim
#define WARPS_PER_CTA 4
#define NTHREADS (WARPS_PER_CTA * 32)
#define NSWEEP 6
#define EPS 1e-6f
#define NB_BANDS 9
#define T_DIM 128
#define B_DIM 8

typedef unsigned long long ull;

// ---- packed 2xfp32 helpers (Blackwell FFMA2 path, PTX-only) ----
__device__ __forceinline__ ull pack2(float x, float y)
{ ull r; asm("mov.b64 %0, {%1, %2};" : "=l"(r) : "f"(x), "f"(y)); return r; }
__device__ __forceinline__ void unpack2(ull v, float& x, float& y)
{ asm("mov.b64 {%0, %1}, %2;" : "=f"(x), "=f"(y) : "l"(v)); }
__device__ __forceinline__ ull mul2(ull a, ull b)
{ ull d; asm("mul.rn.f32x2 %0, %1, %2;" : "=l"(d) : "l"(a), "l"(b)); return d; }
__device__ __forceinline__ ull fma2(ull a, ull b, ull c)
{ ull d; asm("fma.rn.f32x2 %0, %1, %2, %3;" : "=l"(d) : "l"(a), "l"(b), "l"(c)); return d; }
__device__ __forceinline__ ull add2(ull a, ull b)
{ ull d; asm("add.rn.f32x2 %0, %1, %2;" : "=l"(d) : "l"(a), "l"(b)); return d; }

// true single-MUFU approximate reciprocal (NOT __frcp_rn, which adds Newton steps)
__device__ __forceinline__ float rcp_fast(float x)
{ float r; asm("rcp.approx.ftz.f32 %0, %1;" : "=f"(r) : "f"(x)); return r; }

// Jacobi rotation for implicit 2x2 [[np, bpq],[bpq, nq]].
// t = sign(d) * b / (|d| + sqrt(d^2 + b^2)),  d = (nq - np)/2  — exact algebra,
// 3 MUFUs on the dependency chain, no clamps needed (no cancellation).
__device__ __forceinline__ void fastrot(float np, float nq, float bpq,
                                        float& c, float& s)
{
    if (fabsf(bpq) > 1e-20f) {
        float d    = 0.5f * (nq - np);
        float r2   = fmaf(d, d, bpq * bpq);
        float rinv = rsqrtf(r2);                        // MUFU 1
        float den  = fabsf(d) + r2 * rinv;              // |d| + sqrt(d^2+b^2)
        float t    = bpq * rcp_fast(den);               // MUFU 2
        t = (d >= 0.0f) ? t : -t;
        c = rsqrtf(fmaf(t, t, 1.0f));                   // MUFU 3
        s = t * c;
    } else { c = 1.0f; s = 0.0f; }
}

// Warp-cooperative in-place Cholesky (lower) of SPD 32x32 in smem. lane = row.
__device__ __forceinline__ void warp_chol(float* S, int lane)
{
    for (int k = 0; k < N; ++k) {
        float akk = S[k * LDT + k];
        float inv = rsqrtf(fmaxf(akk, 1e-12f));
        __syncwarp();
        float lik = 0.0f;
        if (lane >= k) {
            float v = S[lane * LDT + k];
            lik = (lane == k) ? akk * inv : v * inv;
            S[lane * LDT + k] = lik;
        }
        __syncwarp();
        if (lane > k) {
            for (int j = k + 1; j <= lane; ++j)
                S[lane * LDT + j] -= lik * S[j * LDT + k];
        }
        __syncwarp();
    }
}

// ---------------------------------------------------------------------------
// One WARP per output site:
//   L = chol(A); Lb = chol(B); G = L^{-1} Lb  (lane = column, registers)
//   one-sided Jacobi on G's columns (XOR ordering, packed f32x2 math,
//   software-pipelined shfl exchange, fixed 6 sweeps)
//   mean = Z Z^T with z_c = L g_c * lambda_c^{(w2-1)/2}
// Requires K == 2.
// ---------------------------------------------------------------------------
__global__ void __launch_bounds__(NTHREADS, 6)
wfm_kernel(const float* __restrict__ x, const float* __restrict__ rw,
           float* __restrict__ out, int t_out)
{
    __shared__ float tiles[WARPS_PER_CTA][2][N * LDT];

    const int lane = threadIdx.x & 31;
    const int wrp  = threadIdx.x >> 5;
    float* sA = tiles[wrp][0];                 // A -> L  (upper zeroed later)
    float* sB = tiles[wrp][1];                 // B -> Lb -> Z

    const int site = blockIdx.x * WARPS_PER_CTA + wrp;
    const int band = site % NB_BANDS;
    const int tmp  = site / NB_BANDS;
    const int tt   = tmp % t_out;
    const int b    = tmp / t_out;

    const float* Ma = x + ((size_t)(b * T_DIM + tt) * NB_BANDS + band) * (size_t)(N * N);
    const float* Mb = Ma + (size_t)NB_BANDS * N * N;

    // softmax weight w2 (K == 2)
    float r0 = rw[0], r1 = rw[1];
    float mx = fmaxf(r0, r1);
    float e0 = __expf(r0 - mx), e1 = __expf(r1 - mx);
    const float w2 = e1 / (e0 + e1);

    // load A, B into per-warp tiles (coalesced)
#pragma unroll
    for (int t = 0; t < N; ++t) {
        sA[t * LDT + lane] = Ma[t * N + lane];
        sB[t * LDT + lane] = Mb[t * N + lane];
    }
    __syncwarp();

    warp_chol(sA, lane);                       // sA lower = L
    warp_chol(sB, lane);                       // sB lower = Lb

    // zero strict upper of sA (so Z = L*u can be unconditional later)
#pragma unroll
    for (int j = 0; j < N; ++j)
        if (j > lane) sA[lane * LDT + j] = 0.0f;
    __syncwarp();

    // G = L^{-1} Lb, lane = column c. Lower triangular: u[k] = 0 for k < c.
    float uu[N];
#pragma unroll
    for (int k = 0; k < N; ++k) {
        float acc = sB[k * LDT + lane];
#pragma unroll
        for (int j = 0; j < k; ++j)
            acc -= sA[k * LDT + j] * uu[j];    // broadcast reads of L row k
        float val = acc * __fdividef(1.0f, sA[k * LDT + k]);
        uu[k] = (k >= lane) ? val : 0.0f;
    }

    // pack column into 16 x f32x2
    ull u2[N / 2];
#pragma unroll
    for (int i = 0; i < N / 2; ++i) u2[i] = pack2(uu[2 * i], uu[2 * i + 1]);

    float nu;                                  // ||u||^2, maintained exactly
    {
        ull acc = 0ull;
#pragma unroll
        for (int i = 0; i < N / 2; ++i) acc = fma2(u2[i], u2[i], acc);
        float ax, ay; unpack2(acc, ax, ay);
        nu = ax + ay;
    }

    // ---------------- one-sided Jacobi, XOR ordering, pipelined ------------
    // Prefetch partner data for the first round (m = 1).
    ull pu2[N / 2];
#pragma unroll
    for (int i = 0; i < N / 2; ++i)
        pu2[i] = __shfl_xor_sync(0xffffffffu, u2[i], 1);
    float pn = __shfl_xor_sync(0xffffffffu, nu, 1);

#pragma unroll 1
    for (int sweep = 0; sweep < NSWEEP; ++sweep) {
#pragma unroll 1
        for (int m = 1; m < 32; ++m) {
            const int partner = lane ^ m;
            const int mnext   = (m == 31) ? 1 : m + 1;

            // pair dot, 4 parallel chains (same grouping in both pair lanes)
            ull a0 = 0ull, a1 = 0ull, a2 = 0ull, a3 = 0ull;
#pragma unroll
            for (int i = 0; i < N / 2; i += 4) {
                a0 = fma2(u2[i + 0], pu2[i + 0], a0);
                a1 = fma2(u2[i + 1], pu2[i + 1], a1);
                a2 = fma2(u2[i + 2], pu2[i + 2], a2);
                a3 = fma2(u2[i + 3], pu2[i + 3], a3);
            }
            ull dsum = add2(add2(a0, a1), add2(a2, a3));
            float dx, dy; unpack2(dsum, dx, dy);
            float bu = dx + dy;

            bool isp = lane < partner;
            float np_ = isp ? nu : pn;
            float nq_ = isp ? pn : nu;

            float c, s;
            fastrot(np_, nq_, bu, c, s);
            float ss = isp ? -s : s;

            ull c2  = pack2(c, c);
            ull ss2 = pack2(ss, ss);

            // exact norm rotation identity
            nu = c * c * nu + s * s * pn + 2.0f * ss * c * bu;

            // fused update + next-round shfl (overlaps shfl latency with FMAs)
#pragma unroll
            for (int i = 0; i < N / 2; ++i) {
                u2[i]  = fma2(ss2, pu2[i], mul2(c2, u2[i]));
                pu2[i] = __shfl_xor_sync(0xffffffffu, u2[i], mnext);
            }
            pn = __shfl_xor_sync(0xffffffffu, nu, mnext);
        }
    }

    // eigenvalue = exact final column norm; scale: z = L u * lam^{(w2-1)/2}
    float lam;
    {
        ull acc = 0ull;
#pragma unroll
        for (int i = 0; i < N / 2; ++i) acc = fma2(u2[i], u2[i], acc);
        float ax, ay; unpack2(acc, ax, ay);
        lam = fmaxf(ax + ay, EPS);
    }
    float scale = __expf(0.5f * (w2 - 1.0f) * __logf(lam));
    {
        ull sc2 = pack2(scale, scale);
#pragma unroll
        for (int i = 0; i < N / 2; ++i) u2[i] = mul2(sc2, u2[i]);
    }

    // unpack for the smem products
#pragma unroll
    for (int i = 0; i < N / 2; ++i) unpack2(u2[i], uu[2 * i], uu[2 * i + 1]);

    __syncwarp();
    // Z = L * u (store columns into sB, reuse tile)
    for (int i = 0; i < N; ++i) {
        float acc = 0.0f;
#pragma unroll
        for (int j = 0; j < N; ++j)
            acc = fmaf(sA[i * LDT + j], uu[j], acc);  // upper of L is zeroed
        sB[i * LDT + lane] = acc;
    }
    __syncwarp();

    // mean[i][lane] = sum_c Z[i][c] * Z[lane][c]
    float rr[N];
#pragma unroll
    for (int c = 0; c < N; ++c) rr[c] = sB[lane * LDT + c];

    float* o = out + (size_t)site * (N * N);
    for (int i = 0; i < N; ++i) {
        float acc = 0.0f;
#pragma unroll
        for (int c = 0; c < N; ++c)
            acc = fmaf(sB[i * LDT + c], rr[c], acc);  // broadcast reads
        o[i * N + lane] = acc;                        // coalesced
    }
}

extern "C" void kernel_launch(void* const* d_in, const int* in_sizes, int n_in,
                              void* d_out, int out_size)
{
    const float* x  = (const float*)d_in[0];
    const float* rw = (const float*)d_in[1];
    float* out = (float*)d_out;

    const int K     = in_sizes[1];               // KERNEL_SIZE (= 2 for this problem)
    const int t_out = T_DIM - K + 1;             // 127
    const int sites = B_DIM * t_out * NB_BANDS;  // 9144
    const int nblocks = (sites + WARPS_PER_CTA - 1) / WARPS_PER_CTA;  // 2286

    wfm_kernel<<<nblocks, NTHREADS>>>(x, rw, out, t_out);
}